// round 17
// baseline (speedup 1.0000x reference)
#include <cuda_runtime.h>

#define N_NODES 500000
#define N_EDGES 16000000
#define FULL 0xffffffffu
#define CAP_LOG 7                              // 128 slots per node bucket
#define CAP (1 << CAP_LOG)

// ---------------- device scratch (static; no allocation) ----------------
__device__ int   g_cnt[N_NODES];               // in-degree (also fill cursor)
__device__ int   g_col[(size_t)N_NODES * CAP]; // bucketized CSR: row i at i*CAP
__device__ float g_pa[(size_t)N_NODES * 8];    // projected features (32B records)
__device__ float g_pb[(size_t)N_NODES * 8];
__device__ float g_sa[(size_t)N_NODES * 8];    // precomputed self terms
__device__ float g_sb[(size_t)N_NODES * 8];

// PDL device controls. griddepcontrol.wait is a no-op when the kernel was
// launched without a programmatic dependency -> safe in the fallback path.
__device__ __forceinline__ void gdc_wait() {
    asm volatile("griddepcontrol.wait;" ::: "memory");
}
__device__ __forceinline__ void gdc_launch_dependents() {
    asm volatile("griddepcontrol.launch_dependents;" ::: "memory");
}

// ---------------- fused build: CSR fill (blocks [0,nfill)) + layer-0 proj (rest) ----------------
__global__ void __launch_bounds__(256)
k_build(const int* __restrict__ ei, int E, int nfill,
        const float* __restrict__ x,
        const float* __restrict__ Wl1, const float* __restrict__ Wr1,
        const float* __restrict__ b1,
        float* __restrict__ p0, float* __restrict__ s0) {
    if (blockIdx.x < nfill) {
        int e4 = (blockIdx.x * blockDim.x + threadIdx.x) * 4;
        if (e4 < E) {
            int4 d = *reinterpret_cast<const int4*>(ei + E + e4);  // dst
            int4 s = *reinterpret_cast<const int4*>(ei + e4);      // src
            int q0 = atomicAdd(&g_cnt[d.x], 1); g_col[((size_t)d.x << CAP_LOG) + q0] = s.x;
            int q1 = atomicAdd(&g_cnt[d.y], 1); g_col[((size_t)d.y << CAP_LOG) + q1] = s.y;
            int q2 = atomicAdd(&g_cnt[d.z], 1); g_col[((size_t)d.z << CAP_LOG) + q2] = s.z;
            int q3 = atomicAdd(&g_cnt[d.w], 1); g_col[((size_t)d.w << CAP_LOG) + q3] = s.w;
        }
        gdc_launch_dependents();
        return;
    }
    // ---- layer-0 projection part ----
    __shared__ float sW[105];                 // Wl1(50) | Wr1(50) | b1(5)
    int t = threadIdx.x;
    if (t < 50)       sW[t] = Wl1[t];
    else if (t < 100) sW[t] = Wr1[t - 50];
    else if (t < 105) sW[t] = b1[t - 100];
    __syncthreads();

    int i = (blockIdx.x - nfill) * blockDim.x + t;
    if (i >= N_NODES) { gdc_launch_dependents(); return; }

    float xv[10];
    #pragma unroll
    for (int j = 0; j < 10; j++) xv[j] = x[(size_t)i * 10 + j];

    float pv[5], sv[5];
    #pragma unroll
    for (int d = 0; d < 5; d++) {
        float a = 0.f, bsum = sW[100 + d];
        #pragma unroll
        for (int j = 0; j < 10; j++) {
            a    = fmaf(sW[d * 10 + j],      xv[j], a);
            bsum = fmaf(sW[50 + d * 10 + j], xv[j], bsum);
        }
        pv[d] = a; sv[d] = bsum;
    }
    float4* pr = reinterpret_cast<float4*>(p0 + (size_t)i * 8);
    float4* sr = reinterpret_cast<float4*>(s0 + (size_t)i * 8);
    pr[0] = make_float4(pv[0], pv[1], pv[2], pv[3]);
    pr[1] = make_float4(pv[4], 0.f, 0.f, 0.f);
    sr[0] = make_float4(sv[0], sv[1], sv[2], sv[3]);
    sr[1] = make_float4(sv[4], 0.f, 0.f, 0.f);
    gdc_launch_dependents();
}

// ---------------- fused 5-dim layer, TWO nodes per warp, 64-thread blocks ----------------
// Gather at the L1tex replay floor (proven since R10). No smem, no barrier:
// each lane loads only the weight values its epilogue role needs (pre-wait,
// overlapping the previous layer's tail). LATEWAIT: CSR metadata pre-wait too.
template<int POUT, bool LATEWAIT>
__global__ void __launch_bounds__(64)
k_agg5(const float* __restrict__ p, const float* __restrict__ self,
       float* __restrict__ pout, float* __restrict__ sout,
       const float* __restrict__ Wl, const float* __restrict__ Wr,
       const float* __restrict__ b) {
    int t = threadIdx.x;
    int warp = t >> 5, lane = t & 31;
    int i0 = (blockIdx.x * (blockDim.x >> 5) + warp) * 2;
    if (i0 >= N_NODES) { gdc_wait(); gdc_launch_dependents(); return; }

    int l16  = lane & 15;

    // per-lane weight registers (role-dependent), loaded PRE-wait
    float w0 = 0.f, w1 = 0.f, w2 = 0.f, w3 = 0.f, w4 = 0.f, wb = 0.f;
    if (POUT == 5) {
        if (l16 < 5) {                       // pout row l16 of Wl
            const float* r = Wl + l16 * 5;
            w0 = __ldg(r); w1 = __ldg(r + 1); w2 = __ldg(r + 2);
            w3 = __ldg(r + 3); w4 = __ldg(r + 4);
        } else if (l16 >= 8 && l16 < 13) {   // sout row (l16-8) of Wr + bias
            const float* r = Wr + (l16 - 8) * 5;
            w0 = __ldg(r); w1 = __ldg(r + 1); w2 = __ldg(r + 2);
            w3 = __ldg(r + 3); w4 = __ldg(r + 4); wb = __ldg(b + (l16 - 8));
        }
    } else {
        if (l16 == 0) {
            w0 = __ldg(Wl); w1 = __ldg(Wl + 1); w2 = __ldg(Wl + 2);
            w3 = __ldg(Wl + 3); w4 = __ldg(Wl + 4);
        } else if (l16 == 1) {
            w0 = __ldg(Wr); w1 = __ldg(Wr + 1); w2 = __ldg(Wr + 2);
            w3 = __ldg(Wr + 3); w4 = __ldg(Wr + 4); wb = __ldg(b);
        }
    }

    if (!LATEWAIT) gdc_wait();            // layer 0: CSR itself is dependent

    int2 dg = *reinterpret_cast<const int2*>(g_cnt + i0);   // degA, degB (i0 even)
    int degA = dg.x, degB = dg.y;
    int startA = i0 << CAP_LOG, startB = (i0 + 1) << CAP_LOG;
    int endA = startA + degA, endB = startB + degB;

    int half = lane & 1;                   // 0: p[0..3], 1: p[4..7]
    int epos = lane >> 1;                  // edge slot 0..15

    if (LATEWAIT) gdc_wait();             // p/self become safe to read here

    float4 accA = make_float4(0.f, 0.f, 0.f, 0.f);
    float4 accB = make_float4(0.f, 0.f, 0.f, 0.f);
    int jA = startA + epos, jB = startB + epos;
    while (jA < endA || jB < endB) {
        int sA0 = (jA      < endA) ? __ldg(g_col + jA)      : -1;
        int sA1 = (jA + 16 < endA) ? __ldg(g_col + jA + 16) : -1;
        int sB0 = (jB      < endB) ? __ldg(g_col + jB)      : -1;
        int sB1 = (jB + 16 < endB) ? __ldg(g_col + jB + 16) : -1;
        if (sA0 >= 0) {
            float4 v = __ldg(reinterpret_cast<const float4*>(p + (size_t)sA0 * 8) + half);
            accA.x += v.x; accA.y += v.y; accA.z += v.z; accA.w += v.w;
        }
        if (sB0 >= 0) {
            float4 v = __ldg(reinterpret_cast<const float4*>(p + (size_t)sB0 * 8) + half);
            accB.x += v.x; accB.y += v.y; accB.z += v.z; accB.w += v.w;
        }
        if (sA1 >= 0) {
            float4 v = __ldg(reinterpret_cast<const float4*>(p + (size_t)sA1 * 8) + half);
            accA.x += v.x; accA.y += v.y; accA.z += v.z; accA.w += v.w;
        }
        if (sB1 >= 0) {
            float4 v = __ldg(reinterpret_cast<const float4*>(p + (size_t)sB1 * 8) + half);
            accB.x += v.x; accB.y += v.y; accB.z += v.z; accB.w += v.w;
        }
        jA += 32; jB += 32;
    }

    int h    = lane >> 4;                  // which node this half-warp finishes
    int base = lane & 16;
    int i    = i0 + h;
    int deg  = h ? degB : degA;

    // self load early: its latency hides under the shfl-reduction chain below
    float sv = (l16 < 5) ? __ldg(self + (size_t)i * 8 + l16) : 0.f;

    // fold across halves (xor 16 preserves lane parity)
    accA.x += __shfl_xor_sync(FULL, accA.x, 16);
    accA.y += __shfl_xor_sync(FULL, accA.y, 16);
    accA.z += __shfl_xor_sync(FULL, accA.z, 16);
    accA.w += __shfl_xor_sync(FULL, accA.w, 16);
    accB.x += __shfl_xor_sync(FULL, accB.x, 16);
    accB.y += __shfl_xor_sync(FULL, accB.y, 16);
    accB.z += __shfl_xor_sync(FULL, accB.z, 16);
    accB.w += __shfl_xor_sync(FULL, accB.w, 16);

    // select this half-warp's node, then 3 parity-preserving levels
    float4 u;
    u.x = h ? accB.x : accA.x;
    u.y = h ? accB.y : accA.y;
    u.z = h ? accB.z : accA.z;
    u.w = h ? accB.w : accA.w;
    #pragma unroll
    for (int off = 2; off <= 8; off <<= 1) {
        u.x += __shfl_xor_sync(FULL, u.x, off);
        u.y += __shfl_xor_sync(FULL, u.y, off);
        u.z += __shfl_xor_sync(FULL, u.z, off);
        u.w += __shfl_xor_sync(FULL, u.w, off);
    }

    float s0 = __shfl_sync(FULL, u.x, base);         // even lane: dims0-3
    float s1 = __shfl_sync(FULL, u.y, base);
    float s2 = __shfl_sync(FULL, u.z, base);
    float s3 = __shfl_sync(FULL, u.w, base);
    float s4 = __shfl_sync(FULL, u.x, base | 1);     // odd lane: dim4

    float inv = 1.0f / (float)max(deg, 1);

    float f0 = fmaxf(fmaf(s0, inv, __shfl_sync(FULL, sv, base + 0)), 0.f);
    float f1 = fmaxf(fmaf(s1, inv, __shfl_sync(FULL, sv, base + 1)), 0.f);
    float f2 = fmaxf(fmaf(s2, inv, __shfl_sync(FULL, sv, base + 2)), 0.f);
    float f3 = fmaxf(fmaf(s3, inv, __shfl_sync(FULL, sv, base + 3)), 0.f);
    float f4 = fmaxf(fmaf(s4, inv, __shfl_sync(FULL, sv, base + 4)), 0.f);

    if (POUT == 5) {
        if (l16 < 8) {
            float w = 0.f;
            if (l16 < 5)
                w = fmaf(w0, f0, fmaf(w1, f1, fmaf(w2, f2, fmaf(w3, f3, w4 * f4))));
            pout[(size_t)i * 8 + l16] = w;   // lanes 5-7 keep pads zero
        }
        if (l16 >= 8 && l16 < 13) {
            float w = fmaf(w0, f0, fmaf(w1, f1, fmaf(w2, f2, fmaf(w3, f3,
                      fmaf(w4, f4, wb)))));
            sout[(size_t)i * 8 + (l16 - 8)] = w;
        }
    } else { // POUT == 1: scalar p_next / self_next (stride 1)
        if (l16 == 0) {
            float w = fmaf(w0, f0, fmaf(w1, f1, fmaf(w2, f2, fmaf(w3, f3, w4 * f4))));
            pout[i] = w;
        }
        if (l16 == 1) {
            float w = fmaf(w0, f0, fmaf(w1, f1, fmaf(w2, f2, fmaf(w3, f3,
                      fmaf(w4, f4, wb)))));
            sout[i] = w;
        }
    }
    gdc_launch_dependents();               // stores above are visible to waiters
}

// ---------------- final scalar layer, two nodes per warp, 64-thread blocks ----------------
__global__ void __launch_bounds__(64)
k_agg_final(const float* __restrict__ p, const float* __restrict__ self,
            float* __restrict__ out) {
    int t = threadIdx.x;
    int warp = t >> 5, lane = t & 31;
    int h = lane >> 4, l16 = lane & 15;
    int i = (blockIdx.x * (blockDim.x >> 5) + warp) * 2 + h;
    if (i - h >= N_NODES) { gdc_wait(); return; }

    int deg = g_cnt[i];                    // CSR metadata: pre-wait
    int start = i << CAP_LOG, end = start + deg;

    gdc_wait();                            // p9/self9 safe from here

    float acc = 0.f;
    int j = start + l16;
    while (j < end) {
        int c0 = __ldg(g_col + j);
        int c1 = (j + 16 < end) ? __ldg(g_col + j + 16) : -1;
        acc += __ldg(p + c0);
        if (c1 >= 0) acc += __ldg(p + c1);
        j += 32;
    }
    #pragma unroll
    for (int off = 1; off < 16; off <<= 1)
        acc += __shfl_xor_sync(FULL, acc, off);
    if (l16 == 0) {
        float inv = 1.0f / (float)max(deg, 1);
        out[i] = fmaf(acc, inv, __ldg(self + i));
    }
}

// ---------------- host: launch with PDL attribute, fallback to plain ----------------
template<typename K, typename... Args>
static inline void launch_pdl(K kern, int grid, int block, Args... args) {
    cudaLaunchAttribute attr[1];
    attr[0].id = cudaLaunchAttributeProgrammaticStreamSerialization;
    attr[0].val.programmaticStreamSerializationAllowed = 1;
    cudaLaunchConfig_t cfg{};
    cfg.gridDim  = dim3(grid);
    cfg.blockDim = dim3(block);
    cfg.dynamicSmemBytes = 0;
    cfg.stream   = 0;
    cfg.attrs    = attr;
    cfg.numAttrs = 1;
    if (cudaLaunchKernelEx(&cfg, kern, args...) != cudaSuccess) {
        kern<<<grid, block>>>(args...);    // fallback: wait() degrades to no-op
    }
}

// ---------------- launch ----------------
extern "C" void kernel_launch(void* const* d_in, const int* in_sizes, int n_in,
                              void* d_out, int out_size) {
    const float* x    = (const float*)d_in[0];
    const int*   ei   = (const int*)  d_in[1];
    const float* Wl1  = (const float*)d_in[2];
    const float* Wr1  = (const float*)d_in[3];
    const float* b1   = (const float*)d_in[4];
    const float* Wlm  = (const float*)d_in[5];   // [8,5,5]
    const float* Wrm  = (const float*)d_in[6];   // [8,5,5]
    const float* bm   = (const float*)d_in[7];   // [8,5]
    const float* Wl10 = (const float*)d_in[8];   // [1,5]
    const float* Wr10 = (const float*)d_in[9];   // [1,5]
    const float* b10  = (const float*)d_in[10];  // [1]
    float* out = (float*)d_out;

    void *pa, *pb, *sa, *sb_, *pcnt;
    cudaGetSymbolAddress(&pa,   g_pa);
    cudaGetSymbolAddress(&pb,   g_pb);
    cudaGetSymbolAddress(&sa,   g_sa);
    cudaGetSymbolAddress(&sb_,  g_sb);
    cudaGetSymbolAddress(&pcnt, g_cnt);
    float* P[2] = { (float*)pa,  (float*)pb  };
    float* S[2] = { (float*)sa,  (float*)sb_ };

    const int E = N_EDGES;
    int e4blocks = (E / 4 + 255) / 256;      // fill blocks (256 threads)
    int nb       = (N_NODES + 255) / 256;    // proj blocks
    int npairs   = N_NODES / 2;
    int ablocks  = (npairs + 1) / 2;         // 2 nodes/warp, 2 warps/block (64 thr)

    cudaMemsetAsync(pcnt, 0, N_NODES * sizeof(int));
    k_build<<<e4blocks + nb, 256>>>(ei, E, e4blocks, x, Wl1, Wr1, b1, P[0], S[0]);

    // layer 0: CSR is dependent -> early wait variant
    launch_pdl(k_agg5<5, false>, ablocks, 64,
               (const float*)P[0], (const float*)S[0], P[1], S[1],
               Wlm + 0 * 25, Wrm + 0 * 25, bm + 0 * 5);
    int cur = 1;
    // layers 1..7: CSR immutable -> late wait (prologue overlaps prev tail)
    for (int L = 1; L <= 7; ++L) {
        launch_pdl(k_agg5<5, true>, ablocks, 64,
                   (const float*)P[cur], (const float*)S[cur], P[1 - cur], S[1 - cur],
                   Wlm + L * 25, Wrm + L * 25, bm + L * 5);
        cur = 1 - cur;
    }
    // layer 8: pre-project scalar p9/self9 with Wl10/Wr10/b10
    launch_pdl(k_agg5<1, true>, ablocks, 64,
               (const float*)P[cur], (const float*)S[cur], P[1 - cur], S[1 - cur],
               Wl10, Wr10, b10);
    cur = 1 - cur;
    // layer 9 (final, no relu): out = mean(p9) + self9
    launch_pdl(k_agg_final, ablocks, 64,
               (const float*)P[cur], (const float*)S[cur], out);
}